// round 17
// baseline (speedup 1.0000x reference)
#include <cuda_runtime.h>
#include <cuda_fp16.h>
#include <cstdint>

#define BATCH   65536
#define DIM     128
#define NPROTO  512
#define ODIM    8
#define MTILE   128
#define NCHUNK  64
#define NCHUNKS 8
#define NTHREADS 256

#define BTILE   16384                   // one chunk: 64 rows x 256B (h split only)

#define SM_BIAS 0                       // 512 f32
#define SM_NRM  2048                    // 128 f32
#define SM_A    2560                    // h split: 128 rows x 256B = 32768
#define SM_B    (SM_A + 32768)          // 35328; 2 bufs x 16384
#define SM_MBAR (SM_B + 2 * BTILE)      // 68096
#define SM_RED  SM_A
#define SMEM_TOTAL (SM_MBAR + 32)       // 68128

#define P2ROWS   8
#define P2BLOCKS 1024
#define P2SMEM   ((1024 + 16384 + 512) * 4)   // 71680

// g_h PRE-SWIZZLED chunk-major: chunk*8192(half) + r*128 + (d ^ ((r&7)<<3))
__device__ __align__(16) __half g_h[NPROTO * DIM];
__device__ __align__(16) float  g_wf[NPROTO * DIM];  // exact fp32 w
__device__ float g_bias[NPROTO];
__device__ int   g_maxMw = 0;
__device__ int   g_maxW  = 0;
__device__ int   g_nflag;
__device__ int   g_list[BATCH];

// ---------------- helpers ----------------
__device__ __forceinline__ uint32_t smem_u32(const void* p) {
    uint32_t a;
    asm("{ .reg .u64 t; cvta.to.shared.u64 t, %1; cvt.u32.u64 %0, t; }" : "=r"(a) : "l"(p));
    return a;
}
__device__ __forceinline__ void ldsm4(uint32_t* r, uint32_t a) {
    asm volatile("ldmatrix.sync.aligned.m8n8.x4.shared.b16 {%0,%1,%2,%3}, [%4];"
                 : "=r"(r[0]), "=r"(r[1]), "=r"(r[2]), "=r"(r[3]) : "r"(a));
}
__device__ __forceinline__ void mma16816(float* d, const uint32_t* a, const uint32_t* b) {
    asm volatile(
        "mma.sync.aligned.m16n8k16.row.col.f32.f16.f16.f32 "
        "{%0,%1,%2,%3}, {%4,%5,%6,%7}, {%8,%9}, {%0,%1,%2,%3};"
        : "+f"(d[0]), "+f"(d[1]), "+f"(d[2]), "+f"(d[3])
        : "r"(a[0]), "r"(a[1]), "r"(a[2]), "r"(a[3]), "r"(b[0]), "r"(b[1]));
}
__device__ __forceinline__ void mbar_init(uint32_t a, uint32_t cnt) {
    asm volatile("mbarrier.init.shared.b64 [%0], %1;" :: "r"(a), "r"(cnt) : "memory");
}
__device__ __forceinline__ void mbar_expect_tx(uint32_t a, uint32_t bytes) {
    asm volatile("mbarrier.arrive.expect_tx.shared.b64 _, [%0], %1;"
                 :: "r"(a), "r"(bytes) : "memory");
}
__device__ __forceinline__ void mbar_wait(uint32_t a, uint32_t parity) {
    asm volatile(
        "{\n\t.reg .pred P;\n\t"
        "WL%=:\n\t"
        "mbarrier.try_wait.parity.shared.b64 P, [%0], %1;\n\t"
        "@!P bra WL%=;\n\t}"
        :: "r"(a), "r"(parity) : "memory");
}
__device__ __forceinline__ void bulk_g2s(uint32_t dst, const void* src,
                                         uint32_t bytes, uint32_t mbar) {
    asm volatile(
        "cp.async.bulk.shared::cta.global.mbarrier::complete_tx::bytes [%0], [%1], %2, [%3];"
        :: "r"(dst), "l"(src), "r"(bytes), "r"(mbar) : "memory");
}

// ---------------------------------------------------------------------------
// Prep: g_h (pre-swizzled), g_wf, bias, norm maxima, reset flag counter.
// ---------------------------------------------------------------------------
__global__ void prep_kernel(const float* __restrict__ protos,
                            const float* __restrict__ relevance) {
    int p = blockIdx.x;
    int d = threadIdx.x;
    if (p == 0 && d == 0) g_nflag = 0;

    float r  = relevance[d];
    float pv = protos[p * DIM + d];
    float w  = r * r * pv;

    __half h  = __float2half_rn(w);
    float  Mw = w - __half2float(h);
    int chunk = p >> 6, rr = p & 63;
    g_h[chunk * (NCHUNK * DIM) + rr * DIM + (d ^ ((rr & 7) << 3))] = h;
    g_wf[p * DIM + d] = w;

    float sb = w * pv, sm = Mw * Mw, sw = w * w;
    __shared__ float r0[4], r1[4], r2[4];
    #pragma unroll
    for (int off = 16; off > 0; off >>= 1) {
        sb += __shfl_down_sync(0xffffffffu, sb, off);
        sm += __shfl_down_sync(0xffffffffu, sm, off);
        sw += __shfl_down_sync(0xffffffffu, sw, off);
    }
    if ((d & 31) == 0) { r0[d >> 5] = sb; r1[d >> 5] = sm; r2[d >> 5] = sw; }
    __syncthreads();
    if (d == 0) {
        g_bias[p] = -0.5f * (r0[0] + r0[1] + r0[2] + r0[3]);
        float nm = sqrtf(r1[0] + r1[1] + r1[2] + r1[3]) * 1.0001f;
        float nw = sqrtf(r2[0] + r2[1] + r2[2] + r2[3]) * 1.0001f;
        atomicMax(&g_maxMw, __float_as_int(nm));
        atomicMax(&g_maxW,  __float_as_int(nw));
    }
}

// ---------------------------------------------------------------------------
// Phase 1: hh-only fp16 GEMM on the bulk-copy skeleton + tournament top-2.
//   256 threads, warp tile 16x64, A(h) in registers.
// ---------------------------------------------------------------------------
extern __shared__ char smem[];

__global__ void __launch_bounds__(NTHREADS, 1)
grlvq_phase1(const float* __restrict__ x,
             const float* __restrict__ proto_out,
             float* __restrict__ out) {
    const uint32_t sb = smem_u32(smem);
    const int tid  = threadIdx.x;
    const int wid  = tid >> 5;
    const int lane = tid & 31;
    const int row0 = blockIdx.x * MTILE;
    const int wm = wid * 16;             // 8 M-warps x 16 rows

    if (tid == 0) {
        mbar_init(sb + SM_MBAR + 0, 1);
        mbar_init(sb + SM_MBAR + 8, 1);
    }
    __syncthreads();

    if (tid == 0) {
        #pragma unroll
        for (int c = 0; c < 2; c++) {
            uint32_t mb = sb + SM_MBAR + c * 8;
            mbar_expect_tx(mb, BTILE);
            bulk_g2s(sb + SM_B + c * BTILE,
                     (const char*)g_h + (size_t)c * BTILE, BTILE, mb);
        }
    }

    for (int i = tid; i < NPROTO; i += NTHREADS)
        ((float*)(smem + SM_BIAS))[i] = g_bias[i];

    // ---- A: fp16 high split (stored), row norms for bound ----
    {
        const int r  = tid >> 1;
        const int cb = (tid & 1) * 64;
        const float4* xr = (const float4*)(x + (size_t)(row0 + r) * DIM + cb);
        float sx2 = 0.0f, sm2 = 0.0f;
        #pragma unroll
        for (int g = 0; g < 8; g++) {
            float4 v0 = xr[g * 2], v1 = xr[g * 2 + 1];
            float xv[8] = {v0.x, v0.y, v0.z, v0.w, v1.x, v1.y, v1.z, v1.w};
            uint32_t hh[4];
            #pragma unroll
            for (int q = 0; q < 4; q++) {
                float a0 = xv[2 * q], a1 = xv[2 * q + 1];
                __half h0 = __float2half_rn(a0), h1 = __float2half_rn(a1);
                float m0 = a0 - __half2float(h0), m1 = a1 - __half2float(h1);
                sx2 += a0 * a0 + a1 * a1;
                sm2 += m0 * m0 + m1 * m1;
                hh[q] = ((uint32_t)__half_as_ushort(h1) << 16) | __half_as_ushort(h0);
            }
            uint32_t q0  = (uint32_t)(cb + g * 8) * 2;
            uint32_t off = (uint32_t)r * 256 + (q0 ^ (((uint32_t)r & 7) << 4));
            *(uint4*)(smem + SM_A + off) = make_uint4(hh[0], hh[1], hh[2], hh[3]);
        }
        sx2 += __shfl_xor_sync(0xffffffffu, sx2, 1);
        sm2 += __shfl_xor_sync(0xffffffffu, sm2, 1);
        if ((tid & 1) == 0) {
            float maxMw = __int_as_float(g_maxMw);
            float maxW  = __int_as_float(g_maxW);
            ((float*)(smem + SM_NRM))[r] =
                1.0002f * sqrtf(sx2) * maxMw + 1.0002f * sqrtf(sm2) * maxW + 0.01f;
        }
    }
    __syncthreads();

    // ---- A fragments to registers once (8 ldsm4) ----
    uint32_t ah[8][4];
    {
        const uint32_t arow = (uint32_t)(wm + (lane & 15));
        const uint32_t base = sb + SM_A + arow * 256;
        #pragma unroll
        for (int kk = 0; kk < 8; kk++) {
            uint32_t q0 = (uint32_t)(kk * 32) + ((uint32_t)(lane >> 4)) * 16;
            ldsm4(ah[kk], base + (q0 ^ ((arow & 7) << 4)));
        }
    }

    // per-thread top-2 for 2 row slots
    float v1s[2] = {-3.4e38f, -3.4e38f};
    float v2s[2] = {-3.4e38f, -3.4e38f};
    int   i1s[2] = {0, 0};

    const uint32_t brow_in = (uint32_t)(((lane >> 4) & 1) * 8 + (lane & 7));
    const uint32_t b_kh    = ((uint32_t)(lane >> 3) & 1) * 16;

    for (int c = 0; c < NCHUNKS; c++) {
        mbar_wait(sb + SM_MBAR + (c & 1) * 8, (c >> 1) & 1);
        const uint32_t bbase = sb + SM_B + (c & 1) * BTILE;

        float acc[8][4];
        #pragma unroll
        for (int nt = 0; nt < 8; nt++)
            #pragma unroll
            for (int j = 0; j < 4; j++) acc[nt][j] = 0.0f;

        #pragma unroll
        for (int kk = 0; kk < 8; kk++) {
            uint32_t bH[4][4];
            uint32_t q0 = (uint32_t)(kk * 32) + b_kh;
            #pragma unroll
            for (int nq = 0; nq < 4; nq++) {
                uint32_t brow = brow_in + nq * 16;
                ldsm4(bH[nq], bbase + brow * 256 + (q0 ^ ((brow & 7) << 4)));
            }
            #pragma unroll
            for (int nq = 0; nq < 4; nq++)
                #pragma unroll
                for (int n2 = 0; n2 < 2; n2++)
                    mma16816(acc[nq * 2 + n2], ah[kk], &bH[nq][n2 * 2]);
        }

        // ---- epilogue: bias + exact 4-value tournament top-2 ----
        const float* bias_s = (const float*)(smem + SM_BIAS);
        const int cb0 = c * NCHUNK + (lane & 3) * 2;
        #pragma unroll
        for (int g = 0; g < 4; g++) {            // nt pairs (2g, 2g+1)
            const int c0 = cb0 + g * 16;         // cols c0 < c0+1 < c0+8 < c0+9
            float b0 = bias_s[c0],     b1 = bias_s[c0 + 1];
            float b2b = bias_s[c0 + 8], b3b = bias_s[c0 + 9];
            #pragma unroll
            for (int h = 0; h < 2; h++) {        // rows r, r+8
                float v0 = acc[2 * g    ][2 * h    ] + b0;
                float v1 = acc[2 * g    ][2 * h + 1] + b1;
                float v2 = acc[2 * g + 1][2 * h    ] + b2b;
                float v3 = acc[2 * g + 1][2 * h + 1] + b3b;
                float a  = fmaxf(v0, v1), bb = fminf(v0, v1);
                float cc = fmaxf(v2, v3), dd = fminf(v2, v3);
                float m1 = fmaxf(a, cc);
                float m2 = fmaxf(fminf(a, cc), fmaxf(bb, dd));   // exact 2nd of 4
                int iab = (v1 > v0) ? c0 + 1 : c0;
                int icd = (v3 > v2) ? c0 + 9 : c0 + 8;
                int ig  = (cc > a) ? icd : iab;
                v2s[h] = fmaxf(fminf(v1s[h], m1), fmaxf(v2s[h], m2));
                i1s[h] = (m1 > v1s[h]) ? ig : i1s[h];
                v1s[h] = fmaxf(v1s[h], m1);
            }
        }

        __syncthreads();
        if (c + 2 < NCHUNKS && tid == 0) {
            const int cn = c + 2;
            uint32_t mb = sb + SM_MBAR + (cn & 1) * 8;
            mbar_expect_tx(mb, BTILE);
            bulk_g2s(sb + SM_B + (cn & 1) * BTILE,
                     (const char*)g_h + (size_t)cn * BTILE, BTILE, mb);
        }
    }

    // ---- cross-thread top-2 merge: 4 owners per row ----
    float* rv1 = (float*)(smem + SM_RED);
    int*   ri1 = (int*)(smem + SM_RED + 2048);
    float* rv2 = (float*)(smem + SM_RED + 4096);
    const int slot = lane & 3;
    {
        int r0 = wm + (lane >> 2);
        rv1[r0 * 4 + slot] = v1s[0]; ri1[r0 * 4 + slot] = i1s[0]; rv2[r0 * 4 + slot] = v2s[0];
        rv1[(r0 + 8) * 4 + slot] = v1s[1]; ri1[(r0 + 8) * 4 + slot] = i1s[1];
        rv2[(r0 + 8) * 4 + slot] = v2s[1];
    }
    __syncthreads();

    if (tid < MTILE) {
        float b1 = -3.4e38f, b2 = -3.4e38f;
        int   bi = 0;
        #pragma unroll
        for (int j = 0; j < 4; j++) {
            float v = rv1[tid * 4 + j];
            int  ix = ri1[tid * 4 + j];
            bool g = v > b1;
            b2 = fmaxf(b2, fminf(v, b1));
            b1 = fmaxf(b1, v);
            bi = g ? ix : bi;
        }
        #pragma unroll
        for (int j = 0; j < 4; j++)
            b2 = fmaxf(b2, rv2[tid * 4 + j]);

        float Br = ((const float*)(smem + SM_NRM))[tid];
        bool flag = !(b1 - b2 > 2.0f * Br);

        unsigned m = __ballot_sync(0xffffffffu, flag);
        int cnt = __popc(m);
        if (cnt) {
            int base = 0;
            if (lane == 0) base = atomicAdd(&g_nflag, cnt);
            base = __shfl_sync(0xffffffffu, base, 0);
            if (flag)
                g_list[base + __popc(m & ((1u << lane) - 1u))] = row0 + tid;
        }

        const float4* po = (const float4*)proto_out;
        float4* o = (float4*)(out + (size_t)(row0 + tid) * ODIM);
        o[0] = po[bi * 2];
        o[1] = po[bi * 2 + 1];
    }
}

// ---------------------------------------------------------------------------
// Phase 2: exact fp32 rescore of flagged rows, 8 rows/block, warp-per-row.
// ---------------------------------------------------------------------------
extern __shared__ float s2[];

__global__ void __launch_bounds__(256)
grlvq_phase2(const float* __restrict__ x,
             const float* __restrict__ proto_out,
             float* __restrict__ out) {
    float* sx    = s2;                     // 8 x 128
    float* sw    = s2 + 1024;              // [128 dims][128 protos]
    float* sbias = s2 + 1024 + 16384;      // 512

    const int tid  = threadIdx.x;
    const int wid  = tid >> 5;
    const int lane = tid & 31;
    const int nflag = g_nflag;

    for (int i = tid; i < NPROTO; i += 256) sbias[i] = g_bias[i];

    for (int base = blockIdx.x * P2ROWS; base < nflag; base += P2BLOCKS * P2ROWS) {
        __syncthreads();
        const int nr = min(P2ROWS, nflag - base);

        if (tid < nr * 32) {
            int r = tid >> 5, q = tid & 31;
            int row = g_list[base + r];
            ((float4*)sx)[tid] = ((const float4*)(x + (size_t)row * DIM))[q];
        }

        float bv = -3.4e38f;
        int   bi = 0;

        for (int c = 0; c < 4; c++) {
            __syncthreads();
            {   // transpose-load w chunk: sw[d][p]
                int pr = tid >> 1;
                int d0 = (tid & 1) * 64;
                const float4* wsrc =
                    (const float4*)&g_wf[(size_t)(c * 128 + pr) * DIM + d0];
                #pragma unroll
                for (int q = 0; q < 16; q++) {
                    float4 v = wsrc[q];
                    int d = d0 + q * 4;
                    sw[(d + 0) * 128 + pr] = v.x;
                    sw[(d + 1) * 128 + pr] = v.y;
                    sw[(d + 2) * 128 + pr] = v.z;
                    sw[(d + 3) * 128 + pr] = v.w;
                }
            }
            __syncthreads();

            float a0 = 0.f, a1 = 0.f, a2 = 0.f, a3 = 0.f;
            #pragma unroll 8
            for (int dd = 0; dd < 128; dd++) {
                float xv = sx[wid * 128 + dd];
                float4 w = *(const float4*)&sw[dd * 128 + lane * 4];
                a0 += xv * w.x; a1 += xv * w.y; a2 += xv * w.z; a3 += xv * w.w;
            }
            int p = c * 128 + lane * 4;
            float s0 = a0 + sbias[p];
            float s1 = a1 + sbias[p + 1];
            float s2v = a2 + sbias[p + 2];
            float s3 = a3 + sbias[p + 3];
            if (s0 > bv) { bv = s0; bi = p; }
            if (s1 > bv) { bv = s1; bi = p + 1; }
            if (s2v > bv) { bv = s2v; bi = p + 2; }
            if (s3 > bv) { bv = s3; bi = p + 3; }
        }

        #pragma unroll
        for (int off = 16; off > 0; off >>= 1) {
            float ov = __shfl_down_sync(0xffffffffu, bv, off);
            int   oi = __shfl_down_sync(0xffffffffu, bi, off);
            if (ov > bv || (ov == bv && oi < bi)) { bv = ov; bi = oi; }
        }
        bi = __shfl_sync(0xffffffffu, bi, 0);

        if (wid < nr && lane < 2) {
            int row = g_list[base + wid];
            const float4* po = (const float4*)proto_out;
            ((float4*)(out + (size_t)row * ODIM))[lane] = po[bi * 2 + lane];
        }
    }
}

// ---------------------------------------------------------------------------
extern "C" void kernel_launch(void* const* d_in, const int* in_sizes, int n_in,
                              void* d_out, int out_size) {
    const float* x         = (const float*)d_in[0];
    const float* protos    = (const float*)d_in[1];
    const float* proto_out = (const float*)d_in[2];
    const float* relevance = (const float*)d_in[3];
    float* out = (float*)d_out;

    prep_kernel<<<NPROTO, DIM>>>(protos, relevance);

    cudaFuncSetAttribute(grlvq_phase1,
                         cudaFuncAttributeMaxDynamicSharedMemorySize, SMEM_TOTAL);
    grlvq_phase1<<<BATCH / MTILE, NTHREADS, SMEM_TOTAL>>>(x, proto_out, out);

    cudaFuncSetAttribute(grlvq_phase2,
                         cudaFuncAttributeMaxDynamicSharedMemorySize, P2SMEM);
    grlvq_phase2<<<P2BLOCKS, 256, P2SMEM>>>(x, proto_out, out);
}